// round 5
// baseline (speedup 1.0000x reference)
#include <cuda_runtime.h>
#include <math.h>
#include <stdint.h>

#define Bc 2
#define Sc 2048
#define Ec 1024
#define Hc 16
#define Dc 64
#define Fc 4096
#define Mc (Bc*Sc)          // 4096 rows
#define MB (1024*1024)

// ---------------- scratch (no cudaMalloc allowed) ----------------
__device__ float g_n  [Mc*Ec];
__device__ float g_q  [Mc*Ec];
__device__ float g_k  [Mc*Ec];
__device__ float g_v  [Mc*Ec];
__device__ float g_ctx[Mc*Ec];
__device__ float g_res[Mc*Ec];
__device__ float g_x2 [Mc*Ec];
__device__ float g_f1 [Mc*Fc];
__device__ float g_wr [12*MB];   // tf32-rounded weights: Wq,Wk,Wv,Wo (1M ea), W1 (4M), W2 (4M)

// ---------------- helpers ----------------
__device__ __forceinline__ uint32_t f2tf(float f) {
    uint32_t u;
    asm("cvt.rna.tf32.f32 %0, %1;" : "=r"(u) : "f"(f));
    return u;
}
__device__ __forceinline__ float rtf(float f) { return __uint_as_float(f2tf(f)); }

__device__ __forceinline__ void mma8(float* c, const uint32_t* a, const uint32_t* b) {
    asm volatile(
        "mma.sync.aligned.m16n8k8.row.col.f32.tf32.tf32.f32 "
        "{%0,%1,%2,%3}, {%4,%5,%6,%7}, {%8,%9}, {%0,%1,%2,%3};\n"
        : "+f"(c[0]), "+f"(c[1]), "+f"(c[2]), "+f"(c[3])
        : "r"(a[0]), "r"(a[1]), "r"(a[2]), "r"(a[3]),
          "r"(b[0]), "r"(b[1]));
}

__device__ __forceinline__ void cp16(uint32_t dst, const float* src) {
    asm volatile("cp.async.cg.shared.global [%0], [%1], 16;" :: "r"(dst), "l"(src));
}
#define CP_COMMIT() asm volatile("cp.async.commit_group;")
#define CP_WAIT0()  asm volatile("cp.async.wait_group 0;")
#define CP_WAIT1()  asm volatile("cp.async.wait_group 1;")

// ---------------- weight rounding pass ----------------
__global__ void __launch_bounds__(256) round_kernel(const float* __restrict__ src,
                                                    float* __restrict__ dst, int n4) {
    int i = blockIdx.x * 256 + threadIdx.x;
    if (i < n4) {
        float4 f = ((const float4*)src)[i];
        f.x = rtf(f.x); f.y = rtf(f.y); f.z = rtf(f.z); f.w = rtf(f.w);
        ((float4*)dst)[i] = f;
    }
}

// ---------------- LayerNorm ----------------
template<bool RND>
__global__ void __launch_bounds__(256) ln_kernel(const float* __restrict__ x,
                                                 const float* __restrict__ g,
                                                 const float* __restrict__ b,
                                                 float* __restrict__ out) {
    int row = blockIdx.x;
    int tid = threadIdx.x;
    const float4* xr = (const float4*)(x + (size_t)row * Ec);
    float4 xv = xr[tid];
    float s  = xv.x + xv.y + xv.z + xv.w;
    float sq = xv.x*xv.x + xv.y*xv.y + xv.z*xv.z + xv.w*xv.w;
    #pragma unroll
    for (int o = 16; o; o >>= 1) {
        s  += __shfl_xor_sync(0xffffffffu, s,  o);
        sq += __shfl_xor_sync(0xffffffffu, sq, o);
    }
    __shared__ float ws[8], wq[8];
    __shared__ float s_mu, s_rstd;
    int lane = tid & 31, wid = tid >> 5;
    if (lane == 0) { ws[wid] = s; wq[wid] = sq; }
    __syncthreads();
    if (tid == 0) {
        float S = 0.f, Q = 0.f;
        #pragma unroll
        for (int i = 0; i < 8; i++) { S += ws[i]; Q += wq[i]; }
        float mu  = S * (1.0f / Ec);
        float var = Q * (1.0f / Ec) - mu * mu;
        s_mu = mu;
        s_rstd = rsqrtf(var + 1e-5f);
    }
    __syncthreads();
    float mu = s_mu, rstd = s_rstd;
    float4 gv = ((const float4*)g)[tid];
    float4 bv = ((const float4*)b)[tid];
    float4 ov;
    ov.x = (xv.x - mu) * rstd * gv.x + bv.x;
    ov.y = (xv.y - mu) * rstd * gv.y + bv.y;
    ov.z = (xv.z - mu) * rstd * gv.z + bv.z;
    ov.w = (xv.w - mu) * rstd * gv.w + bv.w;
    if (RND) { ov.x = rtf(ov.x); ov.y = rtf(ov.y); ov.z = rtf(ov.z); ov.w = rtf(ov.w); }
    ((float4*)(out + (size_t)row * Ec))[tid] = ov;
}

// ---------------- tf32 TC GEMM: 128x128x32, 8 warps, 3-stage cp.async ----------------
enum { EP_PLAIN = 0, EP_HEADS = 1, EP_RES = 2, EP_GELU = 3 };

#define BM 128
#define BN 128
#define BK 32
#define LDA 36      // bank = (4m + c) % 32 conflict-free
#define LDB 136     // bank = (8c + n) % 32 conflict-free
#define STG_A (BM * LDA)            // 4608 floats
#define STG_B (BK * LDB)            // 4352 floats
#define STG   (STG_A + STG_B)       // 8960 floats
#define NSTAGE 3
#define TG_SMEM (NSTAGE * STG * 4)  // 107520 bytes

template<int EP>
__global__ void __launch_bounds__(256, 2) tgemm(const float* __restrict__ A,
                                                const float* __restrict__ W,
                                                const float* __restrict__ bias,
                                                const float* __restrict__ res,
                                                float* __restrict__ C,
                                                int M, int N, int K) {
    extern __shared__ float sh[];
    uint32_t smem_u = (uint32_t)__cvta_generic_to_shared(sh);

    int tid  = threadIdx.x;
    int lane = tid & 31;
    int w    = tid >> 5;
    int wm   = (w & 3) * 32;
    int wn   = (w >> 2) * 64;
    int row0 = blockIdx.y * BM;
    int col0 = blockIdx.x * BN;

    const float* Ab = A + (size_t)row0 * K;
    const float* Wb = W + col0;

    int ar  = tid >> 3, akc = (tid & 7) * 4;   // + i*32 rows
    int bkr = tid >> 5, bnc = (tid & 31) * 4;  // + i*8 rows

    auto issue = [&](int k0, int s) {
        uint32_t sa = smem_u + (uint32_t)(s * STG) * 4u;
        uint32_t sb = sa + (uint32_t)STG_A * 4u;
        #pragma unroll
        for (int i = 0; i < 4; i++) {
            int r = ar + i * 32;
            cp16(sa + (uint32_t)(r * LDA + akc) * 4u, Ab + (size_t)r * K + k0 + akc);
            int kr = bkr + i * 8;
            cp16(sb + (uint32_t)(kr * LDB + bnc) * 4u, Wb + (size_t)(k0 + kr) * N + bnc);
        }
        CP_COMMIT();
    };

    float acc[2][8][4];
    #pragma unroll
    for (int mi = 0; mi < 2; mi++)
        #pragma unroll
        for (int ni = 0; ni < 8; ni++)
            #pragma unroll
            for (int q = 0; q < 4; q++) acc[mi][ni][q] = 0.f;

    int nk = K / BK;
    issue(0, 0);
    issue(BK, 1);

    int r_ = lane >> 2, c_ = lane & 3;
    int st = 0;
    for (int kt = 0; kt < nk; kt++) {
        if (kt + 1 < nk) { CP_WAIT1(); } else { CP_WAIT0(); }
        __syncthreads();
        if (kt + 2 < nk) {
            int s2 = st + 2; if (s2 >= NSTAGE) s2 -= NSTAGE;
            issue((kt + 2) * BK, s2);
        }

        const uint32_t* Sa = (const uint32_t*)(sh + st * STG);
        const uint32_t* Sb = Sa + STG_A;

        #pragma unroll
        for (int ks = 0; ks < 4; ks++) {
            int kb = ks * 8;
            uint32_t af[2][4], bf[8][2];
            #pragma unroll
            for (int mi = 0; mi < 2; mi++) {
                int m = wm + mi * 16 + r_;
                af[mi][0] = Sa[m * LDA + kb + c_];
                af[mi][1] = Sa[(m + 8) * LDA + kb + c_];
                af[mi][2] = Sa[m * LDA + kb + c_ + 4];
                af[mi][3] = Sa[(m + 8) * LDA + kb + c_ + 4];
            }
            #pragma unroll
            for (int ni = 0; ni < 8; ni++) {
                int n = wn + ni * 8 + r_;
                bf[ni][0] = Sb[(kb + c_) * LDB + n];
                bf[ni][1] = Sb[(kb + c_ + 4) * LDB + n];
            }
            #pragma unroll
            for (int mi = 0; mi < 2; mi++)
                #pragma unroll
                for (int ni = 0; ni < 8; ni++)
                    mma8(acc[mi][ni], af[mi], bf[ni]);
        }
        if (++st == NSTAGE) st = 0;
    }

    // ---- epilogue ----
    int c2 = (lane & 3) * 2;
    #pragma unroll
    for (int mi = 0; mi < 2; mi++) {
        #pragma unroll
        for (int ni = 0; ni < 8; ni++) {
            #pragma unroll
            for (int h = 0; h < 2; h++) {
                int row = row0 + wm + mi * 16 + r_ + h * 8;
                int col = col0 + wn + ni * 8 + c2;
                float v0 = acc[mi][ni][h * 2 + 0] + bias[col];
                float v1 = acc[mi][ni][h * 2 + 1] + bias[col + 1];
                if (EP == EP_GELU) {
                    v0 = 0.5f * v0 * (1.f + erff(v0 * 0.70710678118654752f));
                    v1 = 0.5f * v1 * (1.f + erff(v1 * 0.70710678118654752f));
                }
                if (EP == EP_RES) {
                    v0 += res[(size_t)row * N + col];
                    v1 += res[(size_t)row * N + col + 1];
                }
                if (EP == EP_HEADS || EP == EP_GELU) { v0 = rtf(v0); v1 = rtf(v1); }
                if (EP == EP_HEADS) {
                    int bb = row >> 11, ss = row & 2047;
                    int hh = col >> 6,  dd = col & 63;
                    *(float2*)&C[(((size_t)(bb * Hc + hh)) * Sc + ss) * Dc + dd] =
                        make_float2(v0, v1);
                } else {
                    *(float2*)&C[(size_t)row * N + col] = make_float2(v0, v1);
                }
            }
        }
    }
}

// ---------------- tf32 TC flash attention: double-buffered cp.async K/V ----------------
#define LDK 68
#define LDV 72
#define LDP 68
#define KV_STG (64*LDK + 64*LDV)                 // floats per stage
#define ATTN_SMEM ((2*KV_STG + 64*LDP) * 4)      // 89088 bytes

__global__ void __launch_bounds__(128, 2) attn_tc(const float* __restrict__ Q,
                                                  const float* __restrict__ K,
                                                  const float* __restrict__ V,
                                                  float* __restrict__ ctx) {
    extern __shared__ uint32_t smu[];
    uint32_t smem_u = (uint32_t)__cvta_generic_to_shared(smu);
    uint32_t* Ps = smu + 2 * KV_STG;

    int tid = threadIdx.x, lane = tid & 31, w = tid >> 5;
    int r_ = lane >> 2, c_ = lane & 3;
    int qt = (int)gridDim.x - 1 - (int)blockIdx.x;
    int bh = blockIdx.y;
    int q0 = qt * 64;

    const float* Qb = Q + (size_t)bh * Sc * Dc;
    const float* Kb = K + (size_t)bh * Sc * Dc;
    const float* Vb = V + (size_t)bh * Sc * Dc;

    auto issue_kv = [&](int k0, int s) {
        uint32_t kb_ = smem_u + (uint32_t)(s * KV_STG) * 4u;
        uint32_t vb_ = kb_ + (uint32_t)(64 * LDK) * 4u;
        #pragma unroll
        for (int it = 0; it < 8; it++) {
            int idx = tid + it * 128;
            int r = idx >> 4, d4 = (idx & 15) * 4;
            cp16(kb_ + (uint32_t)(r * LDK + d4) * 4u, Kb + (size_t)(k0 + r) * Dc + d4);
            cp16(vb_ + (uint32_t)(r * LDV + d4) * 4u, Vb + (size_t)(k0 + r) * Dc + d4);
        }
        CP_COMMIT();
    };

    issue_kv(0, 0);

    // ---- stage Q (pre-scaled; q_ is tf32-exact, x0.125 exact) ----
    #pragma unroll
    for (int it = 0; it < 8; it++) {
        int idx = tid + it * 128;
        int r = idx >> 4, d4 = (idx & 15) * 4;
        float4 f = *(const float4*)(Qb + (size_t)(q0 + r) * Dc + d4);
        Ps[r * LDP + d4 + 0] = __float_as_uint(f.x * 0.125f);
        Ps[r * LDP + d4 + 1] = __float_as_uint(f.y * 0.125f);
        Ps[r * LDP + d4 + 2] = __float_as_uint(f.z * 0.125f);
        Ps[r * LDP + d4 + 3] = __float_as_uint(f.w * 0.125f);
    }
    __syncthreads();
    uint32_t qf[8][4];
    {
        const uint32_t* pw0 = Ps + w * 16 * LDP;
        #pragma unroll
        for (int kc = 0; kc < 8; kc++) {
            int kb = kc * 8;
            qf[kc][0] = pw0[r_ * LDP + kb + c_];
            qf[kc][1] = pw0[(r_ + 8) * LDP + kb + c_];
            qf[kc][2] = pw0[r_ * LDP + kb + c_ + 4];
            qf[kc][3] = pw0[(r_ + 8) * LDP + kb + c_ + 4];
        }
    }

    float o[8][4];
    #pragma unroll
    for (int nf = 0; nf < 8; nf++)
        #pragma unroll
        for (int q = 0; q < 4; q++) o[nf][q] = 0.f;
    float m0 = -1e30f, m1 = -1e30f, l0 = 0.f, l1 = 0.f;

    uint32_t* pw = Ps + w * 16 * LDP;

    for (int kt = 0; kt <= qt; kt++) {
        CP_WAIT0();
        __syncthreads();   // publish stage kt; prior PV reads of stage kt-1 retired
        if (kt + 1 <= qt) issue_kv((kt + 1) * 64, (kt + 1) & 1);

        const uint32_t* Ks = smu + (kt & 1) * KV_STG;
        const uint32_t* Vs = Ks + 64 * LDK;

        // ---- S = (Q/8) K^T ----
        float sacc[8][4];
        #pragma unroll
        for (int nf = 0; nf < 8; nf++)
            #pragma unroll
            for (int q = 0; q < 4; q++) sacc[nf][q] = 0.f;
        #pragma unroll
        for (int kc = 0; kc < 8; kc++) {
            int kb = kc * 8;
            #pragma unroll
            for (int nf = 0; nf < 8; nf++) {
                uint32_t b[2];
                b[0] = Ks[(nf * 8 + r_) * LDK + kb + c_];
                b[1] = Ks[(nf * 8 + r_) * LDK + kb + c_ + 4];
                mma8(sacc[nf], qf[kc], b);
            }
        }

        if (kt == qt) {
            int rr = w * 16 + r_;
            #pragma unroll
            for (int nf = 0; nf < 8; nf++) {
                int cb = nf * 8 + 2 * c_;
                if (cb     > rr)     sacc[nf][0] = -1e30f;
                if (cb + 1 > rr)     sacc[nf][1] = -1e30f;
                if (cb     > rr + 8) sacc[nf][2] = -1e30f;
                if (cb + 1 > rr + 8) sacc[nf][3] = -1e30f;
            }
        }

        float mx0 = -1e30f, mx1 = -1e30f;
        #pragma unroll
        for (int nf = 0; nf < 8; nf++) {
            mx0 = fmaxf(mx0, fmaxf(sacc[nf][0], sacc[nf][1]));
            mx1 = fmaxf(mx1, fmaxf(sacc[nf][2], sacc[nf][3]));
        }
        mx0 = fmaxf(mx0, __shfl_xor_sync(0xffffffffu, mx0, 1));
        mx0 = fmaxf(mx0, __shfl_xor_sync(0xffffffffu, mx0, 2));
        mx1 = fmaxf(mx1, __shfl_xor_sync(0xffffffffu, mx1, 1));
        mx1 = fmaxf(mx1, __shfl_xor_sync(0xffffffffu, mx1, 2));
        float mn0 = fmaxf(m0, mx0), mn1 = fmaxf(m1, mx1);
        float es0 = __expf(m0 - mn0), es1 = __expf(m1 - mn1);
        m0 = mn0; m1 = mn1;
        float ls0 = 0.f, ls1 = 0.f;
        #pragma unroll
        for (int nf = 0; nf < 8; nf++) {
            sacc[nf][0] = __expf(sacc[nf][0] - mn0);
            sacc[nf][1] = __expf(sacc[nf][1] - mn0);
            sacc[nf][2] = __expf(sacc[nf][2] - mn1);
            sacc[nf][3] = __expf(sacc[nf][3] - mn1);
            ls0 += sacc[nf][0] + sacc[nf][1];
            ls1 += sacc[nf][2] + sacc[nf][3];
        }
        ls0 += __shfl_xor_sync(0xffffffffu, ls0, 1);
        ls0 += __shfl_xor_sync(0xffffffffu, ls0, 2);
        ls1 += __shfl_xor_sync(0xffffffffu, ls1, 1);
        ls1 += __shfl_xor_sync(0xffffffffu, ls1, 2);
        l0 = l0 * es0 + ls0;
        l1 = l1 * es1 + ls1;
        #pragma unroll
        for (int nf = 0; nf < 8; nf++) {
            o[nf][0] *= es0; o[nf][1] *= es0;
            o[nf][2] *= es1; o[nf][3] *= es1;
        }

        #pragma unroll
        for (int nf = 0; nf < 8; nf++) {
            int cb = nf * 8 + 2 * c_;
            pw[r_ * LDP + cb]           = __float_as_uint(sacc[nf][0]);
            pw[r_ * LDP + cb + 1]       = __float_as_uint(sacc[nf][1]);
            pw[(r_ + 8) * LDP + cb]     = __float_as_uint(sacc[nf][2]);
            pw[(r_ + 8) * LDP + cb + 1] = __float_as_uint(sacc[nf][3]);
        }
        __syncwarp();

        #pragma unroll
        for (int kc = 0; kc < 8; kc++) {
            int kb = kc * 8;
            uint32_t af[4];
            af[0] = pw[r_ * LDP + kb + c_];
            af[1] = pw[(r_ + 8) * LDP + kb + c_];
            af[2] = pw[r_ * LDP + kb + c_ + 4];
            af[3] = pw[(r_ + 8) * LDP + kb + c_ + 4];
            #pragma unroll
            for (int nf = 0; nf < 8; nf++) {
                uint32_t b[2];
                b[0] = Vs[(kb + c_) * LDV + nf * 8 + r_];
                b[1] = Vs[(kb + c_ + 4) * LDV + nf * 8 + r_];
                mma8(o[nf], af, b);
            }
        }
        __syncwarp();
    }

    int bb = bh >> 4, hh = bh & 15;
    int row0 = q0 + w * 16 + r_;
    float il0 = 1.f / l0, il1 = 1.f / l1;
    #pragma unroll
    for (int nf = 0; nf < 8; nf++) {
        int col = hh * 64 + nf * 8 + 2 * c_;
        *(float2*)&ctx[((size_t)bb * Sc + row0) * Ec + col] =
            make_float2(rtf(o[nf][0] * il0), rtf(o[nf][1] * il0));
        *(float2*)&ctx[((size_t)bb * Sc + row0 + 8) * Ec + col] =
            make_float2(rtf(o[nf][2] * il1), rtf(o[nf][3] * il1));
    }
}

// ---------------- launch ----------------
extern "C" void kernel_launch(void* const* d_in, const int* in_sizes, int n_in,
                              void* d_out, int out_size) {
    const float* x    = (const float*)d_in[0];
    const float* Wq   = (const float*)d_in[2];
    const float* bq   = (const float*)d_in[3];
    const float* Wk   = (const float*)d_in[4];
    const float* bk   = (const float*)d_in[5];
    const float* Wv   = (const float*)d_in[6];
    const float* bv   = (const float*)d_in[7];
    const float* Wo   = (const float*)d_in[8];
    const float* bo   = (const float*)d_in[9];
    const float* W1   = (const float*)d_in[10];
    const float* b1   = (const float*)d_in[11];
    const float* W2   = (const float*)d_in[12];
    const float* b2   = (const float*)d_in[13];
    const float* ln1g = (const float*)d_in[14];
    const float* ln1b = (const float*)d_in[15];
    const float* ln2g = (const float*)d_in[16];
    const float* ln2b = (const float*)d_in[17];
    float* out = (float*)d_out;

    float *n_, *q_, *k_, *v_, *ctx_, *res_, *x2_, *f1_, *wr_;
    cudaGetSymbolAddress((void**)&n_,   g_n);
    cudaGetSymbolAddress((void**)&q_,   g_q);
    cudaGetSymbolAddress((void**)&k_,   g_k);
    cudaGetSymbolAddress((void**)&v_,   g_v);
    cudaGetSymbolAddress((void**)&ctx_, g_ctx);
    cudaGetSymbolAddress((void**)&res_, g_res);
    cudaGetSymbolAddress((void**)&x2_,  g_x2);
    cudaGetSymbolAddress((void**)&f1_,  g_f1);
    cudaGetSymbolAddress((void**)&wr_,  g_wr);

    float* wq_ = wr_;
    float* wk_ = wr_ + 1*MB;
    float* wv_ = wr_ + 2*MB;
    float* wo_ = wr_ + 3*MB;
    float* w1_ = wr_ + 4*MB;
    float* w2_ = wr_ + 8*MB;

    cudaFuncSetAttribute(tgemm<EP_HEADS>, cudaFuncAttributeMaxDynamicSharedMemorySize, TG_SMEM);
    cudaFuncSetAttribute(tgemm<EP_RES>,   cudaFuncAttributeMaxDynamicSharedMemorySize, TG_SMEM);
    cudaFuncSetAttribute(tgemm<EP_GELU>,  cudaFuncAttributeMaxDynamicSharedMemorySize, TG_SMEM);
    cudaFuncSetAttribute(attn_tc, cudaFuncAttributeMaxDynamicSharedMemorySize, ATTN_SMEM);

    // 0. pre-round weights to tf32 (rna) so in-GEMM truncation is exact
    round_kernel<<<(1*MB/4)/256, 256>>>(Wq, wq_, 1*MB/4);
    round_kernel<<<(1*MB/4)/256, 256>>>(Wk, wk_, 1*MB/4);
    round_kernel<<<(1*MB/4)/256, 256>>>(Wv, wv_, 1*MB/4);
    round_kernel<<<(1*MB/4)/256, 256>>>(Wo, wo_, 1*MB/4);
    round_kernel<<<(4*MB/4)/256, 256>>>(W1, w1_, 4*MB/4);
    round_kernel<<<(4*MB/4)/256, 256>>>(W2, w2_, 4*MB/4);

    // 1. LN1 (output tf32-rounded: feeds GEMMs only)
    ln_kernel<true><<<Mc, 256>>>(x, ln1g, ln1b, n_);

    // 2. Q/K/V projections -> [B,H,S,D] (outputs tf32-rounded)
    tgemm<EP_HEADS><<<dim3(Ec/BN, Mc/BM), 256, TG_SMEM>>>(n_, wq_, bq, nullptr, q_, Mc, Ec, Ec);
    tgemm<EP_HEADS><<<dim3(Ec/BN, Mc/BM), 256, TG_SMEM>>>(n_, wk_, bk, nullptr, k_, Mc, Ec, Ec);
    tgemm<EP_HEADS><<<dim3(Ec/BN, Mc/BM), 256, TG_SMEM>>>(n_, wv_, bv, nullptr, v_, Mc, Ec, Ec);

    // 3. Flash attention (tf32 TC) -> ctx [B,S,E] (rounded)
    attn_tc<<<dim3(Sc/64, Bc*Hc), 128, ATTN_SMEM>>>(q_, k_, v_, ctx_);

    // 4. Wo projection + residual with x (full fp32 residual)
    tgemm<EP_RES><<<dim3(Ec/BN, Mc/BM), 256, TG_SMEM>>>(ctx_, wo_, bo, x, res_, Mc, Ec, Ec);

    // 5. LN2 (NOT rounded: x2 is also the final residual)
    ln_kernel<false><<<Mc, 256>>>(res_, ln2g, ln2b, x2_);

    // 6. FFN1 + exact GELU (output rounded)
    tgemm<EP_GELU><<<dim3(Fc/BN, Mc/BM), 256, TG_SMEM>>>(x2_, w1_, b1, nullptr, f1_, Mc, Fc, Ec);

    // 7. FFN2 + bias + residual(x2) -> out
    tgemm<EP_RES><<<dim3(Ec/BN, Mc/BM), 256, TG_SMEM>>>(f1_, w2_, b2, x2_, out, Mc, Ec, Fc);
}